// round 8
// baseline (speedup 1.0000x reference)
#include <cuda_runtime.h>
#include <cuda_fp16.h>
#include <cstdint>

#define B_    16
#define T_    8
#define KBANK 64
#define COUT  128
#define CIN   128
#define HH    64
#define WW    64
#define HP    68
#define WP    68
#define PPW   (COUT * CIN * 25)        // 409600

// ---------------- device scratch (allocation-free) ----------------
__device__ float g_lp[(size_t)B_ * PPW];                       // fp32 [b][o][c][tap]
__device__ unsigned g_Ah[(size_t)B_ * 25 * COUT * (CIN / 2)];  // half2 [b][tap][o][cpair]
__device__ unsigned g_xph[(size_t)B_ * (CIN / 2) * HP * WP];   // half2 [b][cpair][hp][wp]

// ---------------- PTX helpers ----------------
__device__ __forceinline__ uint32_t smem_u32(const void* p) {
    uint32_t a;
    asm("{ .reg .u64 t; cvta.to.shared.u64 t, %1; cvt.u32.u64 %0, t; }" : "=r"(a) : "l"(p));
    return a;
}
#define CP16(smem, gmem) \
    asm volatile("cp.async.cg.shared.global [%0], [%1], 16;" :: "r"(smem), "l"(gmem))
#define CP_COMMIT() asm volatile("cp.async.commit_group;" ::: "memory")
#define CP_WAIT3()  asm volatile("cp.async.wait_group 3;" ::: "memory")
#define CP_WAIT0()  asm volatile("cp.async.wait_group 0;" ::: "memory")

#define MMA16816(c, a, b0v, b1v) \
    asm volatile("mma.sync.aligned.m16n8k16.row.col.f32.f16.f16.f32 " \
        "{%0,%1,%2,%3}, {%4,%5,%6,%7}, {%8,%9}, {%0,%1,%2,%3};" \
        : "+f"((c)[0]), "+f"((c)[1]), "+f"((c)[2]), "+f"((c)[3]) \
        : "r"((a)[0]), "r"((a)[1]), "r"((a)[2]), "r"((a)[3]), "r"(b0v), "r"(b1v))

#define LDMX4(r, addr) \
    asm volatile("ldmatrix.sync.aligned.m8n8.x4.shared.b16 {%0,%1,%2,%3}, [%4];" \
        : "=r"((r)[0]), "=r"((r)[1]), "=r"((r)[2]), "=r"((r)[3]) : "r"(addr))

// ---------------------------------------------------------------------------
// K1: fused coeff + lp:  g_lp[b][p] = sum_k (mean_t tf[b,t,k]) * W[k][p]
// ---------------------------------------------------------------------------
__global__ __launch_bounds__(256) void lp_kernel(const float* __restrict__ W,
                                                 const float* __restrict__ tf) {
    __shared__ float sc[B_ * KBANK];
    int tid = threadIdx.x;
    for (int i = tid; i < B_ * KBANK; i += 256) {
        int b = i >> 6, k = i & 63;
        float s = 0.f;
#pragma unroll
        for (int t = 0; t < T_; t++) s += tf[(b * T_ + t) * KBANK + k];
        sc[i] = s * (1.0f / (float)T_);
    }
    __syncthreads();
    size_t p = (size_t)blockIdx.x * 256 + tid;
    float acc[B_];
#pragma unroll
    for (int b = 0; b < B_; b++) acc[b] = 0.f;
    for (int k = 0; k < KBANK; k++) {
        float wv = W[(size_t)k * PPW + p];
#pragma unroll
        for (int b = 0; b < B_; b++) acc[b] = fmaf(sc[b * KBANK + k], wv, acc[b]);
    }
#pragma unroll
    for (int b = 0; b < B_; b++) g_lp[(size_t)b * PPW + p] = acc[b];
}

// ---------------------------------------------------------------------------
// K2: g_Ah[b][tap][o][cp] = half2(lp[b][o][2cp][tap], lp[b][o][2cp+1][tap])
// ---------------------------------------------------------------------------
__global__ __launch_bounds__(64) void atrans_kernel() {
    int o = blockIdx.x, b = blockIdx.y, cp = threadIdx.x;
    const float* src = g_lp + (((size_t)b * COUT + o) * CIN + 2 * cp) * 25;
    unsigned* dst = g_Ah + ((size_t)b * 25 * COUT + o) * 64 + cp;
#pragma unroll 5
    for (int ij = 0; ij < 25; ij++) {
        __half2 h = __floats2half2_rn(src[ij], src[25 + ij]);
        dst[(size_t)ij * COUT * 64] = *(unsigned*)&h;
    }
}

// ---------------------------------------------------------------------------
// K3: g_xph[b][cp][hp][wp] = half2(x[b][2cp][h][w], x[b][2cp+1][h][w]), pad 0
// ---------------------------------------------------------------------------
__global__ __launch_bounds__(256) void xpad_kernel(const float* __restrict__ x) {
    const int cp = blockIdx.x, b = blockIdx.y;
    const float* x0 = x + ((size_t)(b * CIN + 2 * cp) * HH) * WW;
    const float* x1 = x0 + HH * WW;
    unsigned* dst = g_xph + ((size_t)(b * 64 + cp) * HP) * WP;
    for (int i = threadIdx.x; i < HP * WP; i += 256) {
        int hp = i / WP, wp = i - hp * WP;
        int h = hp - 2, w = wp - 2;
        float v0 = 0.f, v1 = 0.f;
        if ((unsigned)h < HH && (unsigned)w < WW) {
            v0 = x0[h * WW + w];
            v1 = x1[h * WW + w];
        }
        __half2 hh = __floats2half2_rn(v0, v1);
        dst[i] = *(unsigned*)&hh;
    }
}

// ---------------------------------------------------------------------------
// K4: conv, 25 tap-GEMMs, mma m16n8k16 fp16/fp32.
// CTA = (b, 2 rows): D[128 cout, 128 px]; 256 thr, 8 warps = 4M x 2N,
// warp tile 32 cout x 64 px. A: 5-buffer ring, staged 3 taps ahead,
// ONE commit group per iteration, wait_group 3. B: double-buffered per
// cc chunk, next chunk staged at tap 12. A frags via ldmatrix.x4.
// smem 103.4 KB -> 2 CTA/SM.
// ---------------------------------------------------------------------------
#define AP   20                        // A pitch (words)
#define ABUF 2560                      // words per A buffer (128*20)
#define BP   408                       // B pitch per cpair (6*68 words)
#define BBUF 6528                      // words per B buffer (16*408)
#define SBOFF (5 * ABUF)               // 12800
#define SMW  (SBOFF + 2 * BBUF)        // 25856 words = 103424 B

// stage A tile for global tap index T (cc=T/25, tap=T%25) into ring buf T%5
__device__ __forceinline__ void stage_a(uint32_t sb, const unsigned* Abase, int T) {
    const int cc = T / 25, tap = T - cc * 25;
    const uint32_t dbase = sb + (uint32_t)((T % 5) * ABUF) * 4;
#pragma unroll
    for (int i = 0; i < 2; i++) {
        int idx = threadIdx.x + (i << 8);
        int o = idx >> 2, f = idx & 3;
        const unsigned* src = Abase + ((size_t)tap * COUT + o) * 64 + cc * 16 + f * 4;
        CP16(dbase + (uint32_t)(o * AP + f * 4) * 4, src);
    }
}

__device__ __forceinline__ void stage_b(uint32_t sb, const unsigned* Xbase,
                                        int cc, int bbuf, int h0) {
    const uint32_t dbase = sb + (uint32_t)(SBOFF + bbuf * BBUF) * 4;
    for (int idx = threadIdx.x; idx < 1632; idx += 256) {
        int cp = idx / 102, rem = idx - cp * 102;
        int r = rem / 17, f = rem - r * 17;
        const unsigned* src = Xbase + (size_t)(cc * 16 + cp) * HP * WP
                                    + (h0 + r) * WP + f * 4;
        CP16(dbase + (uint32_t)(cp * BP + r * WP + f * 4) * 4, src);
    }
}

__global__ __launch_bounds__(256, 2) void conv_kernel(float* __restrict__ out) {
    extern __shared__ uint32_t sm[];
    const uint32_t sb = smem_u32(sm);
    const int tid = threadIdx.x;
    const int lane = tid & 31;
    const int wid = tid >> 5;
    const int g = lane >> 2, t = lane & 3;
    const int wm = wid & 3;            // 4 M-warps (32 couts each)
    const int wn = wid >> 2;           // 2 N-warps (one output row each)
    const int b = blockIdx.y, h0 = blockIdx.x * 2;

    const unsigned* Abase = g_Ah + (size_t)b * 25 * COUT * 64;
    const unsigned* Xbase = g_xph + (size_t)b * 64 * HP * WP;

    // ldmatrix lane address within an A tile (verified mapping, R6)
    const uint32_t a_lane = (uint32_t)((wm * 32 + (lane & 15)) * AP + (lane >> 4) * 4) * 4;

    float acc[2][8][4];
#pragma unroll
    for (int mt = 0; mt < 2; mt++)
#pragma unroll
        for (int nt = 0; nt < 8; nt++)
#pragma unroll
            for (int q = 0; q < 4; q++) acc[mt][nt][q] = 0.f;

    // ---- prologue: groups G-3 (B0 + A0), G-2 (A1), G-1 (A2) ----
    stage_b(sb, Xbase, 0, 0, h0);
    stage_a(sb, Abase, 0); CP_COMMIT();
    stage_a(sb, Abase, 1); CP_COMMIT();
    stage_a(sb, Abase, 2); CP_COMMIT();

    for (int T = 0; T < 100; T++) {
        const int cc = T / 25, tap = T - cc * 25;
        // stage ahead (lead 3) + mid-chunk B prefetch; exactly one group per iter
        if (T + 3 < 100) stage_a(sb, Abase, T + 3);
        if (tap == 12 && cc < 3) stage_b(sb, Xbase, cc + 1, (cc + 1) & 1, h0);
        CP_COMMIT();
        CP_WAIT3();
        __syncthreads();

        const int di = tap / 5, dj = tap % 5;
        const uint32_t abuf = sb + (uint32_t)((T % 5) * ABUF) * 4 + a_lane;
        const uint32_t* sB = sm + SBOFF + (cc & 1) * BBUF;
        const int pixbase = (wn + di) * WP + dj + g;

#pragma unroll
        for (int kk = 0; kk < 2; kk++) {
            uint32_t a[2][4];
            LDMX4(a[0], abuf + (uint32_t)(kk * 8) * 4);
            LDMX4(a[1], abuf + (uint32_t)(16 * AP + kk * 8) * 4);
            const uint32_t* bp0 = sB + (kk * 8 + t) * BP + pixbase;
            const uint32_t* bp1 = bp0 + 4 * BP;
#pragma unroll
            for (int nt = 0; nt < 8; nt++) {
                uint32_t b0 = bp0[nt * 8], b1 = bp1[nt * 8];
                MMA16816(acc[0][nt], a[0], b0, b1);
                MMA16816(acc[1][nt], a[1], b0, b1);
            }
        }
        __syncthreads();   // protect SA ring buf (reused at T+2) & SB
    }
    CP_WAIT0();

    // ---- epilogue ----
    const int h = h0 + wn;
#pragma unroll
    for (int mt = 0; mt < 2; mt++) {
#pragma unroll
        for (int rr = 0; rr < 2; rr++) {
            int cout = wm * 32 + mt * 16 + g + rr * 8;
            float* op = out + (((size_t)b * COUT + cout) * HH + h) * WW;
#pragma unroll
            for (int nt = 0; nt < 8; nt++) {
                float2 v = make_float2(acc[mt][nt][rr * 2], acc[mt][nt][rr * 2 + 1]);
                *(float2*)(op + nt * 8 + 2 * t) = v;
            }
        }
    }
}

// ---------------------------------------------------------------------------
extern "C" void kernel_launch(void* const* d_in, const int* in_sizes, int n_in,
                              void* d_out, int out_size) {
    (void)in_sizes; (void)n_in; (void)out_size;
    const float* x  = (const float*)d_in[0];   // (16,128,64,64)
    const float* tf = (const float*)d_in[1];   // (16,8,64)
    const float* W  = (const float*)d_in[2];   // (64,128,128,5,5)
    float* out = (float*)d_out;                // (16,128,64,64)

    cudaFuncSetAttribute(conv_kernel, cudaFuncAttributeMaxDynamicSharedMemorySize,
                         SMW * 4);

    lp_kernel<<<PPW / 256, 256>>>(W, tf);
    atrans_kernel<<<dim3(COUT, B_), 64>>>();
    xpad_kernel<<<dim3(64, B_), 256>>>(x);
    conv_kernel<<<dim3(HH / 2, B_), 256, SMW * 4>>>(out);
}

// round 9
// speedup vs baseline: 1.0162x; 1.0162x over previous
#include <cuda_runtime.h>
#include <cuda_fp16.h>
#include <cstdint>

#define B_    16
#define T_    8
#define KBANK 64
#define COUT  128
#define CIN   128
#define HH    64
#define WW    64
#define HP    68
#define WP    68
#define PPW   (COUT * CIN * 25)        // 409600

// ---------------- device scratch (allocation-free) ----------------
__device__ float g_lp[(size_t)B_ * PPW];                       // fp32 [b][o][c][tap]
__device__ unsigned g_Ah[(size_t)B_ * 25 * COUT * (CIN / 2)];  // half2 [b][tap][o][cpair]
__device__ unsigned g_xph[(size_t)B_ * (CIN / 2) * HP * WP];   // half2 [b][cpair][hp][wp]

// ---------------- PTX helpers ----------------
__device__ __forceinline__ uint32_t smem_u32(const void* p) {
    uint32_t a;
    asm("{ .reg .u64 t; cvta.to.shared.u64 t, %1; cvt.u32.u64 %0, t; }" : "=r"(a) : "l"(p));
    return a;
}
#define CP16(smem, gmem) \
    asm volatile("cp.async.cg.shared.global [%0], [%1], 16;" :: "r"(smem), "l"(gmem))
#define CP_COMMIT() asm volatile("cp.async.commit_group;" ::: "memory")
#define CP_WAIT1()  asm volatile("cp.async.wait_group 1;" ::: "memory")
#define CP_WAIT0()  asm volatile("cp.async.wait_group 0;" ::: "memory")

#define MMA16816(c, a, b0v, b1v) \
    asm volatile("mma.sync.aligned.m16n8k16.row.col.f32.f16.f16.f32 " \
        "{%0,%1,%2,%3}, {%4,%5,%6,%7}, {%8,%9}, {%0,%1,%2,%3};" \
        : "+f"((c)[0]), "+f"((c)[1]), "+f"((c)[2]), "+f"((c)[3]) \
        : "r"((a)[0]), "r"((a)[1]), "r"((a)[2]), "r"((a)[3]), "r"(b0v), "r"(b1v))

#define LDMX4(r, addr) \
    asm volatile("ldmatrix.sync.aligned.m8n8.x4.shared.b16 {%0,%1,%2,%3}, [%4];" \
        : "=r"((r)[0]), "=r"((r)[1]), "=r"((r)[2]), "=r"((r)[3]) : "r"(addr))

// ---------------------------------------------------------------------------
// K1: fused coeff + lp:  g_lp[b][p] = sum_k (mean_t tf[b,t,k]) * W[k][p]
// ---------------------------------------------------------------------------
__global__ __launch_bounds__(256) void lp_kernel(const float* __restrict__ W,
                                                 const float* __restrict__ tf) {
    __shared__ float sc[B_ * KBANK];
    int tid = threadIdx.x;
    for (int i = tid; i < B_ * KBANK; i += 256) {
        int b = i >> 6, k = i & 63;
        float s = 0.f;
#pragma unroll
        for (int t = 0; t < T_; t++) s += tf[(b * T_ + t) * KBANK + k];
        sc[i] = s * (1.0f / (float)T_);
    }
    __syncthreads();
    size_t p = (size_t)blockIdx.x * 256 + tid;
    float acc[B_];
#pragma unroll
    for (int b = 0; b < B_; b++) acc[b] = 0.f;
    for (int k = 0; k < KBANK; k++) {
        float wv = W[(size_t)k * PPW + p];
#pragma unroll
        for (int b = 0; b < B_; b++) acc[b] = fmaf(sc[b * KBANK + k], wv, acc[b]);
    }
#pragma unroll
    for (int b = 0; b < B_; b++) g_lp[(size_t)b * PPW + p] = acc[b];
}

// ---------------------------------------------------------------------------
// K2: g_Ah[b][tap][o][cp] = half2(lp[b][o][2cp][tap], lp[b][o][2cp+1][tap])
// ---------------------------------------------------------------------------
__global__ __launch_bounds__(64) void atrans_kernel() {
    int o = blockIdx.x, b = blockIdx.y, cp = threadIdx.x;
    const float* src = g_lp + (((size_t)b * COUT + o) * CIN + 2 * cp) * 25;
    unsigned* dst = g_Ah + ((size_t)b * 25 * COUT + o) * 64 + cp;
#pragma unroll 5
    for (int ij = 0; ij < 25; ij++) {
        __half2 h = __floats2half2_rn(src[ij], src[25 + ij]);
        dst[(size_t)ij * COUT * 64] = *(unsigned*)&h;
    }
}

// ---------------------------------------------------------------------------
// K3: g_xph[b][cp][hp][wp] = half2(x[b][2cp][h][w], x[b][2cp+1][h][w]), pad 0
// ---------------------------------------------------------------------------
__global__ __launch_bounds__(256) void xpad_kernel(const float* __restrict__ x) {
    const int cp = blockIdx.x, b = blockIdx.y;
    const float* x0 = x + ((size_t)(b * CIN + 2 * cp) * HH) * WW;
    const float* x1 = x0 + HH * WW;
    unsigned* dst = g_xph + ((size_t)(b * 64 + cp) * HP) * WP;
    for (int i = threadIdx.x; i < HP * WP; i += 256) {
        int hp = i / WP, wp = i - hp * WP;
        int h = hp - 2, w = wp - 2;
        float v0 = 0.f, v1 = 0.f;
        if ((unsigned)h < HH && (unsigned)w < WW) {
            v0 = x0[h * WW + w];
            v1 = x1[h * WW + w];
        }
        __half2 hh = __floats2half2_rn(v0, v1);
        dst[i] = *(unsigned*)&hh;
    }
}

// ---------------------------------------------------------------------------
// K4: conv, 25 tap-GEMMs, mma m16n8k16 fp16/fp32.
// CTA = (b, 1 output row): D[128 cout, 64 px]; 256 thr, 8 warps = 4M x 2N,
// warp tile 32 cout x 32 px (acc 32 regs -> headroom for LDS hoisting).
// A: 3-buffer ring, lead-1, ONE commit + ONE syncthreads per tap.
// B: halo 5 rows x 68 x 16 cp, pitch 344 (conflict-free), double-buffered,
// next chunk staged at tap 12. 74.75 KB smem -> 3 CTAs/SM.
// ---------------------------------------------------------------------------
#define AP   20                        // A pitch (words)
#define ABUF 2560                      // words per A buffer (128*20)
#define BP   344                       // B pitch per cpair (5*68=340 +4 pad)
#define BBUF (16 * BP)                 // 5504 words per B buffer
#define SBOFF (3 * ABUF)               // 7680
#define SMW  (SBOFF + 2 * BBUF)        // 18688 words = 74752 B

// stage A tile for global step T (cc=T/25, tap=T%25) into ring buf T%3
__device__ __forceinline__ void stage_a(uint32_t sb, const unsigned* Abase, int T) {
    const int cc = T / 25, tap = T - cc * 25;
    const uint32_t dbase = sb + (uint32_t)((T % 3) * ABUF) * 4;
#pragma unroll
    for (int i = 0; i < 2; i++) {
        int idx = threadIdx.x + (i << 8);          // < 512
        int o = idx >> 2, f = idx & 3;
        const unsigned* src = Abase + ((size_t)tap * COUT + o) * 64 + cc * 16 + f * 4;
        CP16(dbase + (uint32_t)(o * AP + f * 4) * 4, src);
    }
}

// stage B halo (5 rows x 68 x 16 cp) for chunk cc into buffer cc&1
__device__ __forceinline__ void stage_b(uint32_t sb, const unsigned* Xbase,
                                        int cc, int h0) {
    const uint32_t dbase = sb + (uint32_t)(SBOFF + (cc & 1) * BBUF) * 4;
    for (int idx = threadIdx.x; idx < 1360; idx += 256) {
        int cp = idx / 85, rem = idx - cp * 85;
        int r = rem / 17, f = rem - r * 17;
        const unsigned* src = Xbase + (size_t)(cc * 16 + cp) * HP * WP
                                    + (h0 + r) * WP + f * 4;
        CP16(dbase + (uint32_t)(cp * BP + r * WP + f * 4) * 4, src);
    }
}

__global__ __launch_bounds__(256, 3) void conv_kernel(float* __restrict__ out) {
    extern __shared__ uint32_t sm[];
    const uint32_t sb = smem_u32(sm);
    const int tid = threadIdx.x;
    const int lane = tid & 31;
    const int wid = tid >> 5;
    const int g = lane >> 2, t = lane & 3;
    const int wm = wid & 3;            // 4 M-warps (32 couts each)
    const int wn = wid >> 2;           // 2 N-warps (32 px each)
    const int w0 = wn * 32;
    const int b = blockIdx.y, h0 = blockIdx.x;

    const unsigned* Abase = g_Ah + (size_t)b * 25 * COUT * 64;
    const unsigned* Xbase = g_xph + (size_t)b * 64 * HP * WP;

    // ldmatrix lane address within an A tile (rows = couts, proven mapping)
    const uint32_t a_lane = (uint32_t)((wm * 32 + (lane & 15)) * AP + (lane >> 4) * 4) * 4;

    float acc[2][4][4];
#pragma unroll
    for (int mt = 0; mt < 2; mt++)
#pragma unroll
        for (int nt = 0; nt < 4; nt++)
#pragma unroll
            for (int q = 0; q < 4; q++) acc[mt][nt][q] = 0.f;

    // prologue: group { B(0), A(0) }
    stage_b(sb, Xbase, 0, h0);
    stage_a(sb, Abase, 0);
    CP_COMMIT();

    for (int T = 0; T < 100; T++) {
        const int cc = T / 25, tap = T - cc * 25;
        // one group per iter: A(T+1) (+ B(cc+1) at tap 12)
        if (T + 1 < 100) stage_a(sb, Abase, T + 1);
        if (tap == 12 && cc < 3) stage_b(sb, Xbase, cc + 1, h0);
        CP_COMMIT();
        CP_WAIT1();          // A(T)'s group (committed previous iter) complete
        __syncthreads();     // also separates compute(T-1) from stage(T+1) reuse

        const int di = tap / 5, dj = tap % 5;
        const uint32_t abuf = sb + (uint32_t)((T % 3) * ABUF) * 4 + a_lane;
        const uint32_t* sB = sm + SBOFF + (cc & 1) * BBUF;
        const int pixbase = di * WP + dj + w0 + g;

#pragma unroll
        for (int kk = 0; kk < 2; kk++) {
            uint32_t a[2][4];
            LDMX4(a[0], abuf + (uint32_t)(kk * 8) * 4);
            LDMX4(a[1], abuf + (uint32_t)(16 * AP + kk * 8) * 4);
            const uint32_t* bp0 = sB + (kk * 8 + t) * BP + pixbase;
            const uint32_t* bp1 = bp0 + 4 * BP;
#pragma unroll
            for (int nt = 0; nt < 4; nt++) {
                uint32_t b0 = bp0[nt * 8], b1 = bp1[nt * 8];
                MMA16816(acc[0][nt], a[0], b0, b1);
                MMA16816(acc[1][nt], a[1], b0, b1);
            }
        }
    }
    CP_WAIT0();

    // ---- epilogue ----
#pragma unroll
    for (int mt = 0; mt < 2; mt++) {
#pragma unroll
        for (int rr = 0; rr < 2; rr++) {
            int cout = wm * 32 + mt * 16 + g + rr * 8;
            float* op = out + (((size_t)b * COUT + cout) * HH + h0) * WW + w0;
#pragma unroll
            for (int nt = 0; nt < 4; nt++) {
                float2 v = make_float2(acc[mt][nt][rr * 2], acc[mt][nt][rr * 2 + 1]);
                *(float2*)(op + nt * 8 + 2 * t) = v;
            }
        }
    }
}

// ---------------------------------------------------------------------------
extern "C" void kernel_launch(void* const* d_in, const int* in_sizes, int n_in,
                              void* d_out, int out_size) {
    (void)in_sizes; (void)n_in; (void)out_size;
    const float* x  = (const float*)d_in[0];   // (16,128,64,64)
    const float* tf = (const float*)d_in[1];   // (16,8,64)
    const float* W  = (const float*)d_in[2];   // (64,128,128,5,5)
    float* out = (float*)d_out;                // (16,128,64,64)

    cudaFuncSetAttribute(conv_kernel, cudaFuncAttributeMaxDynamicSharedMemorySize,
                         SMW * 4);

    lp_kernel<<<PPW / 256, 256>>>(W, tf);
    atrans_kernel<<<dim3(COUT, B_), 64>>>();
    xpad_kernel<<<dim3(64, B_), 256>>>(x);
    conv_kernel<<<dim3(HH, B_), 256, SMW * 4>>>(out);
}

// round 10
// speedup vs baseline: 1.0504x; 1.0337x over previous
#include <cuda_runtime.h>
#include <cuda_fp16.h>
#include <cstdint>

#define B_    16
#define T_    8
#define KBANK 64
#define COUT  128
#define CIN   128
#define HH    64
#define WW    64
#define HP    68
#define WP    68
#define PPW   (COUT * CIN * 25)        // 409600

// ---------------- device scratch (allocation-free) ----------------
__device__ float g_lp[(size_t)B_ * PPW];                      // fp32 [b][o][c][tap]
// A in fragment-major layout: [b][tap][oblock(8)][kblock(8)][lane(32)][4 words]
__device__ uint4 g_Af[(size_t)B_ * 25 * 8 * 8 * 32];
__device__ unsigned g_xph[(size_t)B_ * (CIN / 2) * HP * WP];  // half2 [b][cp][hp][wp]

// ---------------- PTX helpers ----------------
__device__ __forceinline__ uint32_t smem_u32(const void* p) {
    uint32_t a;
    asm("{ .reg .u64 t; cvta.to.shared.u64 t, %1; cvt.u32.u64 %0, t; }" : "=r"(a) : "l"(p));
    return a;
}
#define CP16(smem, gmem) \
    asm volatile("cp.async.cg.shared.global [%0], [%1], 16;" :: "r"(smem), "l"(gmem))
#define CP_COMMIT() asm volatile("cp.async.commit_group;" ::: "memory")
#define CP_WAIT0()  asm volatile("cp.async.wait_group 0;" ::: "memory")

#define MMA16816(c, a, b0v, b1v) \
    asm volatile("mma.sync.aligned.m16n8k16.row.col.f32.f16.f16.f32 " \
        "{%0,%1,%2,%3}, {%4,%5,%6,%7}, {%8,%9}, {%0,%1,%2,%3};" \
        : "+f"((c)[0]), "+f"((c)[1]), "+f"((c)[2]), "+f"((c)[3]) \
        : "r"((a).x), "r"((a).y), "r"((a).z), "r"((a).w), "r"(b0v), "r"(b1v))

// ---------------------------------------------------------------------------
// K1: fused coeff + lp:  g_lp[b][p] = sum_k (mean_t tf[b,t,k]) * W[k][p]
// ---------------------------------------------------------------------------
__global__ __launch_bounds__(256) void lp_kernel(const float* __restrict__ W,
                                                 const float* __restrict__ tf) {
    __shared__ float sc[B_ * KBANK];
    int tid = threadIdx.x;
    for (int i = tid; i < B_ * KBANK; i += 256) {
        int b = i >> 6, k = i & 63;
        float s = 0.f;
#pragma unroll
        for (int t = 0; t < T_; t++) s += tf[(b * T_ + t) * KBANK + k];
        sc[i] = s * (1.0f / (float)T_);
    }
    __syncthreads();
    size_t p = (size_t)blockIdx.x * 256 + tid;
    float acc[B_];
#pragma unroll
    for (int b = 0; b < B_; b++) acc[b] = 0.f;
    for (int k = 0; k < KBANK; k++) {
        float wv = W[(size_t)k * PPW + p];
#pragma unroll
        for (int b = 0; b < B_; b++) acc[b] = fmaf(sc[b * KBANK + k], wv, acc[b]);
    }
#pragma unroll
    for (int b = 0; b < B_; b++) g_lp[(size_t)b * PPW + p] = acc[b];
}

// ---------------------------------------------------------------------------
// K2: pack A fragments. grid (25 taps, 16 b), 256 thr.
// word r of [oq][kb][lane]: lane=(g*4+t):
//   r0: half2(lp[o=oq*16+g   ][c=2(kb*8+t)  ..+1]), r1: o+8,
//   r2: cp+4 (c=2(kb*8+t+4)),                      r3: o+8, cp+4
// ---------------------------------------------------------------------------
__global__ __launch_bounds__(256) void apack_kernel() {
    const int tap = blockIdx.x, b = blockIdx.y;
    const float* lpb = g_lp + (size_t)b * PPW + tap;   // [o][c] stride 25
    uint4* dst = g_Af + ((size_t)b * 25 + tap) * 2048;
#pragma unroll
    for (int i = 0; i < 8; i++) {
        int idx = threadIdx.x + (i << 8);              // < 2048
        int oq = idx >> 8, kb = (idx >> 5) & 7, lane = idx & 31;
        int g = lane >> 2, t = lane & 3;
        int o0 = oq * 16 + g;
        int c0 = 2 * (kb * 8 + t);
        const float* p00 = lpb + ((size_t)o0 * CIN + c0) * 25;
        const float* p10 = p00 + (size_t)8 * CIN * 25;
        __half2 r0 = __floats2half2_rn(p00[0],        p00[25]);
        __half2 r1 = __floats2half2_rn(p10[0],        p10[25]);
        __half2 r2 = __floats2half2_rn(p00[8 * 25],   p00[9 * 25]);
        __half2 r3 = __floats2half2_rn(p10[8 * 25],   p10[9 * 25]);
        uint4 v;
        v.x = *(unsigned*)&r0; v.y = *(unsigned*)&r1;
        v.z = *(unsigned*)&r2; v.w = *(unsigned*)&r3;
        dst[idx] = v;
    }
}

// ---------------------------------------------------------------------------
// K3: g_xph[b][cp][hp][wp] = half2(x[b][2cp][h][w], x[b][2cp+1][h][w]), pad 0
// ---------------------------------------------------------------------------
__global__ __launch_bounds__(256) void xpad_kernel(const float* __restrict__ x) {
    const int cp = blockIdx.x, b = blockIdx.y;
    const float* x0 = x + ((size_t)(b * CIN + 2 * cp) * HH) * WW;
    const float* x1 = x0 + HH * WW;
    unsigned* dst = g_xph + ((size_t)(b * 64 + cp) * HP) * WP;
    for (int i = threadIdx.x; i < HP * WP; i += 256) {
        int hp = i / WP, wp = i - hp * WP;
        int h = hp - 2, w = wp - 2;
        float v0 = 0.f, v1 = 0.f;
        if ((unsigned)h < HH && (unsigned)w < WW) {
            v0 = x0[h * WW + w];
            v1 = x1[h * WW + w];
        }
        __half2 hh = __floats2half2_rn(v0, v1);
        dst[i] = *(unsigned*)&hh;
    }
}

// ---------------------------------------------------------------------------
// K4: conv, 25 tap-GEMMs, mma m16n8k16 fp16/fp32.
// CTA = (b, 1 output row): D[128 cout, 64 px]; 256 thr, 8 warps = 4M x 2N,
// warp tile 32 cout x 32 px. A via coalesced LDG.128 fragments (no smem).
// B halo in smem (double-buffered per 32-cin chunk); barriers ONLY at the
// 4 chunk boundaries — warps free-run across the 25 taps of a chunk.
// smem 44 KB -> 3 CTAs/SM.
// ---------------------------------------------------------------------------
#define BP   344                       // B pitch per cpair (5*68=340 +4 pad)
#define BBUF (16 * BP)                 // 5504 words per buffer
#define SMW  (2 * BBUF)                // 11008 words = 44032 B

__device__ __forceinline__ void stage_b(uint32_t sb, const unsigned* Xbase,
                                        int cc, int h0) {
    const uint32_t dbase = sb + (uint32_t)((cc & 1) * BBUF) * 4;
    for (int idx = threadIdx.x; idx < 1360; idx += 256) {
        int cp = idx / 85, rem = idx - cp * 85;
        int r = rem / 17, f = rem - r * 17;
        const unsigned* src = Xbase + (size_t)(cc * 16 + cp) * HP * WP
                                    + (h0 + r) * WP + f * 4;
        CP16(dbase + (uint32_t)(cp * BP + r * WP + f * 4) * 4, src);
    }
}

__global__ __launch_bounds__(256, 3) void conv_kernel(float* __restrict__ out) {
    extern __shared__ uint32_t sm[];
    const uint32_t sb = smem_u32(sm);
    const int tid = threadIdx.x;
    const int lane = tid & 31;
    const int wid = tid >> 5;
    const int g = lane >> 2, t = lane & 3;
    const int wm = wid & 3;            // 4 M-warps (32 couts each)
    const int wn = wid >> 2;           // 2 N-warps (32 px each)
    const int w0 = wn * 32;
    const int b = blockIdx.y, h0 = blockIdx.x;

    // A fragment pointer for this warp: [tap][oblock = wm*2 + mt][kblock][lane]
    const uint4* __restrict__ Aw = g_Af + ((size_t)b * 25 + 0) * 2048
                                 + (size_t)(wm * 2) * 256 + lane;
    const unsigned* Xbase = g_xph + (size_t)b * 64 * HP * WP;

    float acc[2][4][4];
#pragma unroll
    for (int mt = 0; mt < 2; mt++)
#pragma unroll
        for (int nt = 0; nt < 4; nt++)
#pragma unroll
            for (int q = 0; q < 4; q++) acc[mt][nt][q] = 0.f;

    stage_b(sb, Xbase, 0, h0);
    CP_COMMIT();

#pragma unroll 1
    for (int cc = 0; cc < 4; cc++) {
        CP_WAIT0();
        __syncthreads();
        const uint32_t* sB = sm + (cc & 1) * BBUF;

#pragma unroll 5
        for (int tap = 0; tap < 25; tap++) {
            if (tap == 12 && cc < 3) { stage_b(sb, Xbase, cc + 1, h0); CP_COMMIT(); }
            const int di = tap / 5, dj = tap % 5;
            // 4 coalesced LDG.128: (mt, kk)
            const uint4* ap = Aw + (size_t)tap * 2048 + cc * 64;
            uint4 a00 = ap[0];          // mt0 kk0
            uint4 a01 = ap[32];         // mt0 kk1
            uint4 a10 = ap[256];        // mt1 kk0
            uint4 a11 = ap[256 + 32];   // mt1 kk1
            const int pixbase = di * WP + dj + w0 + g;
#pragma unroll
            for (int kk = 0; kk < 2; kk++) {
                const uint32_t* bp0 = sB + (kk * 8 + t) * BP + pixbase;
                const uint32_t* bp1 = bp0 + 4 * BP;
                uint4 a0 = kk ? a01 : a00;
                uint4 a1 = kk ? a11 : a10;
#pragma unroll
                for (int nt = 0; nt < 4; nt++) {
                    uint32_t b0 = bp0[nt * 8], b1 = bp1[nt * 8];
                    MMA16816(acc[0][nt], a0, b0, b1);
                    MMA16816(acc[1][nt], a1, b0, b1);
                }
            }
        }
    }

    // ---- epilogue ----
#pragma unroll
    for (int mt = 0; mt < 2; mt++) {
#pragma unroll
        for (int rr = 0; rr < 2; rr++) {
            int cout = wm * 32 + mt * 16 + g + rr * 8;
            float* op = out + (((size_t)b * COUT + cout) * HH + h0) * WW + w0;
#pragma unroll
            for (int nt = 0; nt < 4; nt++) {
                float2 v = make_float2(acc[mt][nt][rr * 2], acc[mt][nt][rr * 2 + 1]);
                *(float2*)(op + nt * 8 + 2 * t) = v;
            }
        }
    }
}

// ---------------------------------------------------------------------------
extern "C" void kernel_launch(void* const* d_in, const int* in_sizes, int n_in,
                              void* d_out, int out_size) {
    (void)in_sizes; (void)n_in; (void)out_size;
    const float* x  = (const float*)d_in[0];   // (16,128,64,64)
    const float* tf = (const float*)d_in[1];   // (16,8,64)
    const float* W  = (const float*)d_in[2];   // (64,128,128,5,5)
    float* out = (float*)d_out;                // (16,128,64,64)

    cudaFuncSetAttribute(conv_kernel, cudaFuncAttributeMaxDynamicSharedMemorySize,
                         SMW * 4);

    lp_kernel<<<PPW / 256, 256>>>(W, tf);
    apack_kernel<<<dim3(25, B_), 256>>>();
    xpad_kernel<<<dim3(64, B_), 256>>>(x);
    conv_kernel<<<dim3(HH, B_), 256, SMW * 4>>>(out);
}